// round 6
// baseline (speedup 1.0000x reference)
#include <cuda_runtime.h>

#define BB   1024
#define CC   3
#define PROW 4
#define PCOL 5
#define PP   20      // PROW*PCOL
#define HID  32
#define HH   224
#define WW   220
#define PH   56      // HH/PROW
#define PW   44      // WW/PCOL
#define W4   55      // WW/4 float4 per row
#define PW4  11      // PW/4 float4 per column-patch

// score fan-in state (2 halves per image)
__device__ float        g_half_score[BB][2];
__device__ unsigned int g_cnt[BB];            // zero-init; atomicInc wraps to 0

// ---------------------------------------------------------------------------
// grid = (BB, 2), block = (56, 8). Block (b, half) owns image rows
// [half*112, half*112+112) over all 3 channels = row-patches {2h, 2h+1}.
// Its 10 patches are COMPLETE within the block (mean spans C x 56 x 44),
// so contribs need no cross-block traffic; only the scalar score does a
// 2-way fan-in (deterministic fixed-order add).
// ---------------------------------------------------------------------------
__global__ __launch_bounds__(448)
void nam_halfrow_kernel(const float* __restrict__ x,
                        const float* __restrict__ w1,
                        const float* __restrict__ b1,
                        const float* __restrict__ w2,
                        const float* __restrict__ b2,
                        float* __restrict__ out)
{
    const int b    = blockIdx.x;
    const int half = blockIdx.y;
    const int tx   = threadIdx.x;   // 0..55 (55 idle for loads)
    const int ty   = threadIdx.y;   // 0..7

    const float4* base = (const float4*)(x) + (size_t)b * (CC * HH * W4);
    const int h0 = half * (2 * PH);

    float acc[2] = {0.f, 0.f};

    if (tx < W4) {
        #pragma unroll
        for (int c = 0; c < CC; c++) {
            const float4* cb = base + c * (HH * W4);
            #pragma unroll
            for (int pl = 0; pl < 2; pl++) {             // local row-patch
                #pragma unroll
                for (int i = 0; i < PH / 8; i++) {       // 7 row-groups
                    const int h = h0 + pl * PH + i * 8 + ty;
                    float4 v = cb[h * W4 + tx];
                    acc[pl] += (v.x + v.y) + (v.z + v.w);
                }
            }
        }
    }

    __shared__ float part[2][8][56];
    part[0][ty][tx] = acc[0];                            // tx==55 stores 0
    part[1][ty][tx] = acc[1];
    __syncthreads();

    // Warp 0: lanes 0..9 each own one local patch (pl*5 + pc); reduce + MLP.
    const int tid = ty * 56 + tx;
    if (tid < 32) {
        float o = 0.f;
        if (tid < 10) {
            const int pl = tid / PCOL;
            const int pc = tid % PCOL;
            float s = 0.f;
            #pragma unroll
            for (int yy = 0; yy < 8; yy++) {
                float a = 0.f;
                #pragma unroll
                for (int k = 0; k < PW4; k++)
                    a += part[pl][yy][pc * PW4 + k];
                s += a;
            }
            const float f = s * (1.0f / (CC * PH * PW)); // mean over 7392 elems

            const int p = half * 10 + tid;               // global patch index
            o = b2[p];
            const float* w1p = w1 + p * HID;
            const float* b1p = b1 + p * HID;
            const float* w2p = w2 + p * HID;
            #pragma unroll
            for (int k = 0; k < HID; k++) {
                float h = fmaf(f, w1p[k], b1p[k]);
                h = fmaxf(h, 0.0f);
                o = fmaf(h, w2p[k], o);
            }
            out[BB + b * PP + p] = o;                    // contribs section
        }
        // half-score = sum of this block's 10 contribs
        float sc = o;                                    // lanes >= 10 add 0
        #pragma unroll
        for (int off = 16; off > 0; off >>= 1)
            sc += __shfl_down_sync(0xFFFFFFFFu, sc, off);

        if (tid == 0) {
            g_half_score[b][half] = sc;
            __threadfence();                             // publish before arrive
            unsigned int old = atomicInc(&g_cnt[b], 1);  // wraps 0->1->0
            if (old == 1) {                              // last arriver
                float s0 = __ldcg(&g_half_score[b][0]);
                float s1 = __ldcg(&g_half_score[b][1]);
                out[b] = s0 + s1;                        // fixed order: deterministic
            }
        }
    }
}

extern "C" void kernel_launch(void* const* d_in, const int* in_sizes, int n_in,
                              void* d_out, int out_size)
{
    const float* x  = (const float*)d_in[0];
    const float* w1 = (const float*)d_in[1];
    const float* b1 = (const float*)d_in[2];
    const float* w2 = (const float*)d_in[3];
    const float* b2 = (const float*)d_in[4];
    float* out = (float*)d_out;

    nam_halfrow_kernel<<<dim3(BB, 2), dim3(56, 8)>>>(x, w1, b1, w2, b2, out);
}

// round 8
// speedup vs baseline: 1.0624x; 1.0624x over previous
#include <cuda_runtime.h>

#define BB   1024
#define CC   3
#define PROW 4
#define PCOL 5
#define PP   20      // PROW*PCOL
#define HID  32
#define HH   224
#define WW   220
#define PH   56      // HH/PROW
#define PW   44      // WW/PCOL
#define W4   55      // WW/4 float4 per row
#define PW4  11      // PW/4 float4 per column-patch

#define IPB  16      // images per block in the MLP kernel
#define MLPT (IPB * PP)   // 320 threads

// per-(image, patch, channel) partial sums
__device__ float g_scratch[BB * PP * CC];

// ---------------------------------------------------------------------------
// Kernel 1: pooling (identical to the R2 kernel that streamed at ~6.9 TB/s —
// no fences, no atomics in the stream). grid = (BB, CC); block = (56, 8).
// ---------------------------------------------------------------------------
__global__ __launch_bounds__(448)
void nam_pool_kernel(const float* __restrict__ x)
{
    const int b  = blockIdx.x;
    const int c  = blockIdx.y;
    const int tx = threadIdx.x;   // 0..55 (55 idle for loads)
    const int ty = threadIdx.y;   // 0..7

    const float4* base = (const float4*)(x) + (size_t)(b * CC + c) * (HH * W4);

    float acc[PROW] = {0.f, 0.f, 0.f, 0.f};

    if (tx < W4) {
        #pragma unroll
        for (int pr = 0; pr < PROW; pr++) {
            #pragma unroll
            for (int i = 0; i < PH / 8; i++) {          // 7 row-groups
                const int h = pr * PH + i * 8 + ty;
                float4 v = base[h * W4 + tx];
                acc[pr] += (v.x + v.y) + (v.z + v.w);
            }
        }
    }

    __shared__ float part[PROW][8][56];
    #pragma unroll
    for (int pr = 0; pr < PROW; pr++)
        part[pr][ty][tx] = acc[pr];                      // tx==55 stores 0
    __syncthreads();

    const int tid = ty * 56 + tx;
    if (tid < PP) {
        const int pr = tid / PCOL;
        const int pc = tid % PCOL;
        float s = 0.f;
        #pragma unroll
        for (int yy = 0; yy < 8; yy++) {
            float a = 0.f;
            #pragma unroll
            for (int k = 0; k < PW4; k++)
                a += part[pr][yy][pc * PW4 + k];
            s += a;
        }
        g_scratch[(b * PP + tid) * CC + c] = s;
    }
}

// ---------------------------------------------------------------------------
// Kernel 2: MLP, one thread per (image, patch). grid = BB/IPB = 64 blocks,
// block = 320 threads. Weights staged once per block into padded shared
// ([PP][HID+1] -> bank = (p+k) mod 32, conflict-free). Score via shared.
// ---------------------------------------------------------------------------
__global__ __launch_bounds__(MLPT)
void nam_mlp_kernel(const float* __restrict__ w1,
                    const float* __restrict__ b1,
                    const float* __restrict__ w2,
                    const float* __restrict__ b2,
                    float* __restrict__ out)
{
    __shared__ float sw1[PP][HID + 1];
    __shared__ float sb1[PP][HID + 1];
    __shared__ float sw2[PP][HID + 1];
    __shared__ float sb2[PP];
    __shared__ float scon[IPB][PP];

    const int t = threadIdx.x;

    // cooperative weight staging: PP*HID = 640 elems per array, 2 per thread
    for (int idx = t; idx < PP * HID; idx += MLPT) {
        const int p = idx / HID, k = idx % HID;
        sw1[p][k] = w1[idx];
        sb1[p][k] = b1[idx];
        sw2[p][k] = w2[idx];
    }
    if (t < PP) sb2[t] = b2[t];
    __syncthreads();

    const int i = t / PP;                 // local image 0..15
    const int p = t % PP;                 // patch 0..19
    const int b = blockIdx.x * IPB + i;

    const float* sp = &g_scratch[(b * PP + p) * CC];
    const float f = (sp[0] + sp[1] + sp[2]) * (1.0f / (CC * PH * PW));

    float o = sb2[p];
    #pragma unroll
    for (int k = 0; k < HID; k++) {
        float h = fmaf(f, sw1[p][k], sb1[p][k]);
        h = fmaxf(h, 0.0f);
        o = fmaf(h, sw2[p][k], o);
    }
    out[BB + b * PP + p] = o;             // contribs section
    scon[i][p] = o;
    __syncthreads();

    if (t < IPB) {
        float sc = 0.f;
        #pragma unroll
        for (int q = 0; q < PP; q++)
            sc += scon[t][q];
        out[blockIdx.x * IPB + t] = sc;   // score section
    }
}

extern "C" void kernel_launch(void* const* d_in, const int* in_sizes, int n_in,
                              void* d_out, int out_size)
{
    const float* x  = (const float*)d_in[0];
    const float* w1 = (const float*)d_in[1];
    const float* b1 = (const float*)d_in[2];
    const float* w2 = (const float*)d_in[3];
    const float* b2 = (const float*)d_in[4];
    float* out = (float*)d_out;

    nam_pool_kernel<<<dim3(BB, CC), dim3(56, 8)>>>(x);
    nam_mlp_kernel<<<BB / IPB, MLPT>>>(w1, b1, w2, b2, out);
}